// round 8
// baseline (speedup 1.0000x reference)
#include <cuda_runtime.h>
#include <cstdint>

// TreeModel: depth-14 perfect binary heap, 32767 nodes, 16384 leaves, dim 512.
// out[0..16383] = dot(x[i], sum of deltas along root->leaf path)
// out[16384]    = sq[0] + sum_{n>=1} sq[n]/max(heights[n]-heights[parent],1e-7)
//
// PERSISTENT kernel: 296 CTAs (2/SM, one wave) x 256 threads; each CTA loops
// over tiles b = bid, bid+296, ... (tile = level-11 subtree, 8 leaves).
// Depth-2 TMA pipeline over two 50KB smem buffers:
//   buffer slot: [U9|U10|U11|D12 x2|D13 x4|DL x8|XS x8] rows of 2KB.
//   mb0[p]: unique weight rows (18KB)  mb1[p]: leaves+x (32KB)
//   iteration i consumes buffer p=i&1 and then issues tile i+2 into p.
// Levels 0..8 (L2-hot, shared by >=8 tiles) via slice-split LDG + 4KB exchange.
// sq/branch terms folded with owner-CTA + slice gating; sqacc carried in
// registers across tiles; one g_part write per CTA; fence+counter last-CTA
// reduces 296 partials in fixed order. No data atomics -> deterministic.

#define DIM 512
#define N_LEAVES 16384
#define NTILES 2048
#define GRID 296            // 2 per SM on 148 SMs (147+? safe on 152 too)

// float4-unit offsets within one buffer (128 float4 per 2KB row)
#define U9_OFF   0
#define U10_OFF  128
#define U11_OFF  256
#define D12_OFF  384      // 2 rows
#define D13_OFF  640      // 4 rows
#define DL_OFF   1152     // 8 rows
#define XS_OFF   2176     // 8 rows
#define BUF_F4   3200     // 50KB per buffer
#define SP_OFF   6400     // 2-row exchange (shared by both buffers)
#define DYN_SMEM (6656 * 16)

__device__ float g_part[GRID];
__device__ unsigned int g_count = 0;

__device__ __forceinline__ float warp_sum(float v) {
#pragma unroll
    for (int o = 16; o > 0; o >>= 1) v += __shfl_down_sync(0xffffffffu, v, o);
    return v;
}
__device__ __forceinline__ float inv_branch(const float* __restrict__ h, int n) {
    return 1.0f / fmaxf(h[n] - h[(n - 1) >> 1], 1e-7f);
}
__device__ __forceinline__ float sq4(float4 v) {
    return fmaf(v.x, v.x, fmaf(v.y, v.y, fmaf(v.z, v.z, v.w * v.w)));
}
__device__ __forceinline__ float4 add4(float4 a, float4 b) {
    return make_float4(a.x + b.x, a.y + b.y, a.z + b.z, a.w + b.w);
}
__device__ __forceinline__ void bulk_cp(unsigned dst, const float* src, unsigned bytes, unsigned mb) {
    asm volatile("cp.async.bulk.shared::cta.global.mbarrier::complete_tx::bytes [%0], [%1], %2, [%3];"
                 :: "r"(dst), "l"(src), "r"(bytes), "r"(mb) : "memory");
}
__device__ __forceinline__ void mb_wait(unsigned mb, int parity) {
    asm volatile(
        "{\n\t.reg .pred p;\n\t"
        "W_%=:\n\t"
        "mbarrier.try_wait.parity.acquire.cta.shared::cta.b64 p, [%0], %1;\n\t"
        "@!p bra W_%=;\n\t}" :: "r"(mb), "r"(parity) : "memory");
}

// issue the two TMA groups for tile b into buffer p (call from tid==0 only)
__device__ __forceinline__ void issue_tile(unsigned smb, unsigned mb0, unsigned mb1,
                                           int p, int b,
                                           const float* __restrict__ deltas,
                                           const float* __restrict__ x) {
    const unsigned base = smb + (unsigned)(p * BUF_F4) * 16u;
    int a11 = 2047 + b;
    int a10 = (a11 - 1) >> 1;
    int a9  = (a10 - 1) >> 1;
    asm volatile("mbarrier.arrive.expect_tx.shared.b64 _, [%0], %1;" :: "r"(mb0), "r"(18432u));
    asm volatile("mbarrier.arrive.expect_tx.shared.b64 _, [%0], %1;" :: "r"(mb1), "r"(32768u));
    bulk_cp(base + U9_OFF  * 16, deltas + (size_t)a9  * DIM, 2048u,  mb0);
    bulk_cp(base + U10_OFF * 16, deltas + (size_t)a10 * DIM, 2048u,  mb0);
    bulk_cp(base + U11_OFF * 16, deltas + (size_t)a11 * DIM, 2048u,  mb0);
    bulk_cp(base + D12_OFF * 16, deltas + (size_t)(4095 + 2 * b) * DIM, 4096u,  mb0);
    bulk_cp(base + D13_OFF * 16, deltas + (size_t)(8191 + 4 * b) * DIM, 8192u,  mb0);
    bulk_cp(base + DL_OFF  * 16, deltas + (size_t)(N_LEAVES - 1 + 8 * b) * DIM, 16384u, mb1);
    bulk_cp(base + XS_OFF  * 16, x + (size_t)(8 * b) * DIM, 16384u, mb1);
}

__global__ __launch_bounds__(256) void tree_kernel(const float* __restrict__ x,
                                                   const float* __restrict__ deltas,
                                                   const float* __restrict__ heights,
                                                   float* __restrict__ out) {
    extern __shared__ float4 sm[];
    __shared__ float redL[32];        // 8 leaves x 4 warps-in-slice
    __shared__ float redS[8];
    __shared__ int   is_last;
    __shared__ __align__(8) unsigned long long mbar[4];  // mb0[2], mb1[2]

    const int bid  = blockIdx.x;
    const int tid  = threadIdx.x;
    const int col  = tid & 127;
    const int g    = tid >> 7;        // slice 0/1
    const int w    = tid >> 5;
    const int ws   = w & 3;
    const int lane = tid & 31;

    const unsigned smb = (unsigned)__cvta_generic_to_shared(sm);
    unsigned mb0[2], mb1[2];
    mb0[0] = (unsigned)__cvta_generic_to_shared(&mbar[0]);
    mb0[1] = (unsigned)__cvta_generic_to_shared(&mbar[1]);
    mb1[0] = (unsigned)__cvta_generic_to_shared(&mbar[2]);
    mb1[1] = (unsigned)__cvta_generic_to_shared(&mbar[3]);

    if (tid == 0) {
#pragma unroll
        for (int j = 0; j < 4; ++j) {
            unsigned a = (unsigned)__cvta_generic_to_shared(&mbar[j]);
            asm volatile("mbarrier.init.shared.b64 [%0], %1;" :: "r"(a), "r"(1));
        }
        asm volatile("fence.proxy.async.shared::cta;" ::: "memory");
        // prologue: fill both buffers
        issue_tile(smb, mb0[0], mb1[0], 0, bid, deltas, x);
        if (bid + GRID < NTILES)
            issue_tile(smb, mb0[1], mb1[1], 1, bid + GRID, deltas, x);
    }
    __syncthreads();

    int ph0[2] = {0, 0}, ph1[2] = {0, 0};
    float sqacc = 0.f;
    int i = 0;

    for (int b = bid; b < NTILES; b += GRID, ++i) {
        const int p = i & 1;
        const float4* buf = sm + p * BUF_F4;

        int anc[12];
        anc[11] = 2047 + b;
#pragma unroll
        for (int l = 11; l > 0; --l) anc[l - 1] = (anc[l] - 1) >> 1;

        // ---- levels 0..8: slice-split LDG (L2-hot) -------------------------
        {
            float4 s = make_float4(0.f, 0.f, 0.f, 0.f);
#pragma unroll
            for (int l = 0; l <= 8; ++l) {
                if ((l & 1) == g) {
                    float4 v = ((const float4*)(deltas + (size_t)anc[l] * DIM))[col];
                    s = add4(s, v);
                    if ((b & ((1 << (11 - l)) - 1)) == 0) {     // owner tile
                        float inv = (l == 0) ? 1.0f : inv_branch(heights, anc[l]);
                        sqacc = fmaf(sq4(v), inv, sqacc);
                    }
                }
            }
            sm[SP_OFF + g * 128 + col] = s;
        }

        const float inv12 = inv_branch(heights, 4095 + 2 * b + g);
        float inv13[2], inv14[4];
#pragma unroll
        for (int j = 0; j < 2; ++j) inv13[j] = inv_branch(heights, 8191 + 4 * b + 2 * g + j);
#pragma unroll
        for (int j = 0; j < 4; ++j) inv14[j] = inv_branch(heights, N_LEAVES - 1 + 8 * b + 4 * g + j);

        __syncthreads();                                   // S1: SP ready
        float4 cum = add4(sm[SP_OFF + col], sm[SP_OFF + 128 + col]);

        // ---- levels 9..13 from TMA (mb0[p]) --------------------------------
        mb_wait(mb0[p], ph0[p]); ph0[p] ^= 1;
        {
            float4 v9  = buf[U9_OFF  + col];
            float4 v10 = buf[U10_OFF + col];
            float4 v11 = buf[U11_OFF + col];
            if (g == 1 && (b & 3) == 0) sqacc = fmaf(sq4(v9),  inv_branch(heights, anc[9]),  sqacc);
            if (g == 0 && (b & 1) == 0) sqacc = fmaf(sq4(v10), inv_branch(heights, anc[10]), sqacc);
            if (g == 1)                 sqacc = fmaf(sq4(v11), inv_branch(heights, anc[11]), sqacc);
            cum = add4(add4(cum, v9), add4(v10, v11));
        }
        float4 c12;
        {
            float4 v = buf[D12_OFF + g * 128 + col];
            sqacc = fmaf(sq4(v), inv12, sqacc);
            c12 = add4(cum, v);
        }
        float4 c13[2];
#pragma unroll
        for (int j = 0; j < 2; ++j) {
            float4 v = buf[D13_OFF + (2 * g + j) * 128 + col];
            sqacc = fmaf(sq4(v), inv13[j], sqacc);
            c13[j] = add4(c12, v);
        }

        // ---- leaves from TMA (mb1[p]) --------------------------------------
        mb_wait(mb1[p], ph1[p]); ph1[p] ^= 1;
        float acc[4];
#pragma unroll
        for (int j = 0; j < 4; ++j) {
            const int li = 4 * g + j;
            float4 dv = buf[DL_OFF + li * 128 + col];
            float4 xv = buf[XS_OFF + li * 128 + col];
            sqacc = fmaf(sq4(dv), inv14[j], sqacc);
            float4 wv = add4(c13[j >> 1], dv);
            float t;
            t = xv.x * wv.x;
            t = fmaf(xv.y, wv.y, t);
            t = fmaf(xv.z, wv.z, t);
            t = fmaf(xv.w, wv.w, t);
            acc[j] = warp_sum(t);
        }
        if (lane == 0) {
#pragma unroll
            for (int j = 0; j < 4; ++j) redL[(g * 4 + j) * 4 + ws] = acc[j];
        }
        __syncthreads();                                   // S2: buffer consumed

        if (tid < 8) {
            float r = redL[tid * 4] + redL[tid * 4 + 1] + redL[tid * 4 + 2] + redL[tid * 4 + 3];
            out[8 * b + tid] = r;
        }
        // issue tile i+2 into buffer p (freed by S2)
        const int bn = b + 2 * GRID;
        if (tid == 0 && bn < NTILES)
            issue_tile(smb, mb0[p], mb1[p], p, bn, deltas, x);
    }

    // ---------------- per-CTA sq total ---------------------------------------
    sqacc = warp_sum(sqacc);
    if (lane == 0) redS[w] = sqacc;
    __syncthreads();
    if (tid == 0) {
        float t = 0.f;
#pragma unroll
        for (int j = 0; j < 8; ++j) t += redS[j];
        g_part[bid] = t;
        __threadfence();
        unsigned prev = atomicAdd(&g_count, 1u);
        is_last = (prev == GRID - 1) ? 1 : 0;
    }
    __syncthreads();

    // ---------------- last CTA: deterministic final reduce -------------------
    if (is_last) {
        const volatile float* gp = g_part;
        float s = gp[tid];
        if (tid < GRID - 256) s += gp[tid + 256];
        s = warp_sum(s);
        if (lane == 0) redS[w] = s;
        __syncthreads();
        if (tid == 0) {
            float t = 0.f;
#pragma unroll
            for (int j = 0; j < 8; ++j) t += redS[j];
            out[N_LEAVES] = t;
            g_count = 0;               // reset for next graph replay
        }
    }
}

extern "C" void kernel_launch(void* const* d_in, const int* in_sizes, int n_in,
                              void* d_out, int out_size) {
    const float* x       = (const float*)d_in[0];
    const float* deltas  = (const float*)d_in[1];
    const float* heights = (const float*)d_in[2];
    float* out = (float*)d_out;

    cudaFuncSetAttribute(tree_kernel, cudaFuncAttributeMaxDynamicSharedMemorySize, DYN_SMEM);
    tree_kernel<<<GRID, 256, DYN_SMEM>>>(x, deltas, heights, out);
}

// round 9
// speedup vs baseline: 1.0156x; 1.0156x over previous
#include <cuda_runtime.h>
#include <cstdint>

// TreeModel: depth-14 perfect binary heap, 32767 nodes, 16384 leaves, dim 512.
// out[0..16383] = dot(x[i], sum of deltas along root->leaf path)
// out[16384]    = sq[0] + sum_{n>=1} sq[n]/max(heights[n]-heights[parent],1e-7)
//
// 3 kernels, all phases chainless:
//  expandA: 256 level-8 cum rows, each = sum of 9 INDEPENDENT row loads.
//           sq levels 0..8 (owner-row trick) -> g_sqA[256].
//  expandB: 2048 level-11 cum rows = cumA[parent] + 3 independent rows.
//           sq levels 9..11 -> g_sqB[512].
//  stream:  2048 CTAs x 256 (tile = level-11 subtree, 8 leaves), 30KB smem:
//           mb0(TMA): cum row + lvl12 pair + lvl13 quad (14KB)
//           mb1(TMA): 8 leaf delta rows (16KB)
//           x read via 4 independent LDG.128 per thread at the dot.
//           sq levels 12..14 fused -> g_part[2048]; fence+counter last-CTA
//           reduces g_sqA+g_sqB+g_part in fixed order. Deterministic.

#define DIM 512
#define N_LEAVES 16384
#define NTILES 2048

__device__ __align__(128) float g_cumA[256 * DIM];    // level-8 cums (512KB)
__device__ __align__(128) float g_cum[NTILES * DIM];  // level-11 cums (4MB)
__device__ float g_sqA[256];
__device__ float g_sqB[512];
__device__ float g_part[NTILES];
__device__ unsigned int g_count = 0;

__device__ __forceinline__ float warp_sum(float v) {
#pragma unroll
    for (int o = 16; o > 0; o >>= 1) v += __shfl_down_sync(0xffffffffu, v, o);
    return v;
}
__device__ __forceinline__ float inv_branch(const float* __restrict__ h, int n) {
    return 1.0f / fmaxf(h[n] - h[(n - 1) >> 1], 1e-7f);
}
__device__ __forceinline__ float sq4(float4 v) {
    return fmaf(v.x, v.x, fmaf(v.y, v.y, fmaf(v.z, v.z, v.w * v.w)));
}
__device__ __forceinline__ float4 add4(float4 a, float4 b) {
    return make_float4(a.x + b.x, a.y + b.y, a.z + b.z, a.w + b.w);
}
__device__ __forceinline__ void bulk_cp(unsigned dst, const float* src, unsigned bytes, unsigned mb) {
    asm volatile("cp.async.bulk.shared::cta.global.mbarrier::complete_tx::bytes [%0], [%1], %2, [%3];"
                 :: "r"(dst), "l"(src), "r"(bytes), "r"(mb) : "memory");
}
__device__ __forceinline__ void mb_wait(unsigned mb) {
    asm volatile(
        "{\n\t.reg .pred p;\n\t"
        "W_%=:\n\t"
        "mbarrier.try_wait.parity.acquire.cta.shared::cta.b64 p, [%0], 0;\n\t"
        "@!p bra W_%=;\n\t}" :: "r"(mb) : "memory");
}

// ---------------- expandA: level-8 cums (chainless, MLP=9) ------------------
__global__ __launch_bounds__(128) void expandA_kernel(const float* __restrict__ deltas,
                                                      const float* __restrict__ heights) {
    __shared__ float red[4];
    const int r    = blockIdx.x;          // level-8 row 0..255
    const int col  = threadIdx.x;         // float4 column
    const int w    = threadIdx.x >> 5;
    const int lane = threadIdx.x & 31;

    int anc[9];
    anc[8] = 255 + r;
#pragma unroll
    for (int l = 8; l > 0; --l) anc[l - 1] = (anc[l] - 1) >> 1;

    float4 v[9];
#pragma unroll
    for (int l = 0; l <= 8; ++l)                        // 9 independent loads
        v[l] = ((const float4*)(deltas + (size_t)anc[l] * DIM))[col];

    float sqacc = 0.f;
    float4 s = make_float4(0.f, 0.f, 0.f, 0.f);
#pragma unroll
    for (int l = 0; l <= 8; ++l) {
        s = add4(s, v[l]);
        if ((r & ((1 << (8 - l)) - 1)) == 0) {          // owner row for node
            float inv = (l == 0) ? 1.0f : inv_branch(heights, anc[l]);
            sqacc = fmaf(sq4(v[l]), inv, sqacc);
        }
    }
    ((float4*)(g_cumA + (size_t)r * DIM))[col] = s;

    sqacc = warp_sum(sqacc);
    if (lane == 0) red[w] = sqacc;
    __syncthreads();
    if (threadIdx.x == 0) g_sqA[r] = red[0] + red[1] + red[2] + red[3];
}

// ---------------- expandB: level-11 cums (chainless, MLP=4) -----------------
__global__ __launch_bounds__(512) void expandB_kernel(const float* __restrict__ deltas,
                                                      const float* __restrict__ heights) {
    __shared__ float red[16];
    const int tid  = threadIdx.x;
    const int grp  = tid >> 7;            // 0..3
    const int col  = tid & 127;
    const int w    = tid >> 5;
    const int lane = tid & 31;
    const int r    = blockIdx.x * 4 + grp;  // level-11 row 0..2047

    const int n11 = 2047 + r;
    const int n10 = 1023 + (r >> 1);
    const int n9  = 511 + (r >> 2);

    float4 vA  = ((const float4*)(g_cumA + (size_t)(r >> 3) * DIM))[col];
    float4 v9  = ((const float4*)(deltas + (size_t)n9  * DIM))[col];
    float4 v10 = ((const float4*)(deltas + (size_t)n10 * DIM))[col];
    float4 v11 = ((const float4*)(deltas + (size_t)n11 * DIM))[col];

    float sqacc = 0.f;
    if ((r & 3) == 0) sqacc = fmaf(sq4(v9),  inv_branch(heights, n9),  sqacc);
    if ((r & 1) == 0) sqacc = fmaf(sq4(v10), inv_branch(heights, n10), sqacc);
    sqacc = fmaf(sq4(v11), inv_branch(heights, n11), sqacc);

    float4 s = add4(add4(vA, v9), add4(v10, v11));
    ((float4*)(g_cum + (size_t)r * DIM))[col] = s;

    sqacc = warp_sum(sqacc);
    if (lane == 0) red[w] = sqacc;
    __syncthreads();
    if (tid == 0) {
        float t = 0.f;
#pragma unroll
        for (int j = 0; j < 16; ++j) t += red[j];
        g_sqB[blockIdx.x] = t;
    }
}

// ---------------- stream: leaves + dots + final reduce ----------------------
// smem float4 offsets: CUM 0 (1 row), D12 128 (2), D13 384 (4), DL 896 (8)
__global__ __launch_bounds__(256) void stream_kernel(const float* __restrict__ x,
                                                     const float* __restrict__ deltas,
                                                     const float* __restrict__ heights,
                                                     float* __restrict__ out) {
    __shared__ float4 sm[1920];       // 30 KB
    __shared__ float  redL[32];
    __shared__ float  redS[8];
    __shared__ int    is_last;
    __shared__ __align__(8) unsigned long long mbar[2];

    const int b    = blockIdx.x;      // tile = level-11 subtree
    const int tid  = threadIdx.x;
    const int col  = tid & 127;
    const int g    = tid >> 7;        // slice 0/1
    const int w    = tid >> 5;
    const int ws   = w & 3;
    const int lane = tid & 31;

    const unsigned mb0 = (unsigned)__cvta_generic_to_shared(&mbar[0]);
    const unsigned mb1 = (unsigned)__cvta_generic_to_shared(&mbar[1]);
    const unsigned smb = (unsigned)__cvta_generic_to_shared(sm);

    if (tid == 0) {
        asm volatile("mbarrier.init.shared.b64 [%0], %1;" :: "r"(mb0), "r"(1));
        asm volatile("mbarrier.init.shared.b64 [%0], %1;" :: "r"(mb1), "r"(1));
        asm volatile("fence.proxy.async.shared::cta;" ::: "memory");
        asm volatile("mbarrier.arrive.expect_tx.shared.b64 _, [%0], %1;" :: "r"(mb0), "r"(14336u));
        asm volatile("mbarrier.arrive.expect_tx.shared.b64 _, [%0], %1;" :: "r"(mb1), "r"(16384u));
        bulk_cp(smb + 0   * 16, g_cum + (size_t)b * DIM,                    2048u,  mb0);
        bulk_cp(smb + 128 * 16, deltas + (size_t)(4095 + 2 * b) * DIM,      4096u,  mb0);
        bulk_cp(smb + 384 * 16, deltas + (size_t)(8191 + 4 * b) * DIM,      8192u,  mb0);
        bulk_cp(smb + 896 * 16, deltas + (size_t)(N_LEAVES - 1 + 8 * b) * DIM, 16384u, mb1);
    }
    __syncthreads();

    // scalar inv factors (broadcast loads; overlap with TMA flight)
    const float inv12 = inv_branch(heights, 4095 + 2 * b + g);
    float inv13[2], inv14[4];
#pragma unroll
    for (int j = 0; j < 2; ++j) inv13[j] = inv_branch(heights, 8191 + 4 * b + 2 * g + j);
#pragma unroll
    for (int j = 0; j < 4; ++j) inv14[j] = inv_branch(heights, N_LEAVES - 1 + 8 * b + 4 * g + j);

    float sqacc = 0.f;

    // ---- weight path (mb0) --------------------------------------------------
    mb_wait(mb0);
    float4 c12;
    {
        float4 v = sm[128 + g * 128 + col];
        sqacc = fmaf(sq4(v), inv12, sqacc);
        c12 = add4(sm[col], v);
    }
    float4 c13[2];
#pragma unroll
    for (int j = 0; j < 2; ++j) {
        float4 v = sm[384 + (2 * g + j) * 128 + col];
        sqacc = fmaf(sq4(v), inv13[j], sqacc);
        c13[j] = add4(c12, v);
    }

    // ---- leaves (mb1) + x via independent LDG.128 ---------------------------
    mb_wait(mb1);
    float4 xv[4];
#pragma unroll
    for (int j = 0; j < 4; ++j)       // 4 independent global loads, issued first
        xv[j] = ((const float4*)(x + (size_t)(8 * b + 4 * g + j) * DIM))[col];

    float acc[4];
#pragma unroll
    for (int j = 0; j < 4; ++j) {
        const int li = 4 * g + j;
        float4 dv = sm[896 + li * 128 + col];
        sqacc = fmaf(sq4(dv), inv14[j], sqacc);
        float4 wv = add4(c13[j >> 1], dv);
        float t;
        t = xv[j].x * wv.x;
        t = fmaf(xv[j].y, wv.y, t);
        t = fmaf(xv[j].z, wv.z, t);
        t = fmaf(xv[j].w, wv.w, t);
        acc[j] = warp_sum(t);
    }
    if (lane == 0) {
#pragma unroll
        for (int j = 0; j < 4; ++j) redL[(g * 4 + j) * 4 + ws] = acc[j];
    }

    sqacc = warp_sum(sqacc);
    if (lane == 0) redS[w] = sqacc;
    __syncthreads();

    if (tid < 8) {
        float r = redL[tid * 4] + redL[tid * 4 + 1] + redL[tid * 4 + 2] + redL[tid * 4 + 3];
        out[8 * b + tid] = r;
    }
    if (tid == 0) {
        float t = 0.f;
#pragma unroll
        for (int j = 0; j < 8; ++j) t += redS[j];
        g_part[b] = t;
        __threadfence();
        unsigned prev = atomicAdd(&g_count, 1u);
        is_last = (prev == NTILES - 1) ? 1 : 0;
    }
    __syncthreads();

    // ---- last CTA: deterministic final reduce (fixed order) -----------------
    if (is_last) {
        const volatile float* gA = g_sqA;
        const volatile float* gB = g_sqB;
        const volatile float* gp = g_part;
        float s = gA[tid & 255] * ((tid < 256) ? 1.f : 0.f);
        s += gB[tid] + gB[tid + 256];
#pragma unroll
        for (int r = 0; r < 8; ++r) s += gp[tid + 256 * r];
        s = warp_sum(s);
        if (lane == 0) redS[w] = s;
        __syncthreads();
        if (tid == 0) {
            float t = 0.f;
#pragma unroll
            for (int j = 0; j < 8; ++j) t += redS[j];
            out[N_LEAVES] = t;
            g_count = 0;              // reset for next graph replay
        }
    }
}

extern "C" void kernel_launch(void* const* d_in, const int* in_sizes, int n_in,
                              void* d_out, int out_size) {
    const float* x       = (const float*)d_in[0];
    const float* deltas  = (const float*)d_in[1];
    const float* heights = (const float*)d_in[2];
    float* out = (float*)d_out;

    expandA_kernel<<<256, 128>>>(deltas, heights);
    expandB_kernel<<<512, 512>>>(deltas, heights);
    stream_kernel<<<NTILES, 256>>>(x, deltas, heights, out);
}

// round 10
// speedup vs baseline: 1.1620x; 1.1441x over previous
#include <cuda_runtime.h>
#include <cstdint>

// TreeModel: depth-14 perfect binary heap, 32767 nodes, 16384 leaves, dim 512.
// out[0..16383] = dot(x[i], sum of deltas along root->leaf path)
// out[16384]    = sq[0] + sum_{n>=1} sq[n]/max(heights[n]-heights[parent],1e-7)
//
// 2 kernels:
//  expand: 256 CTAs x 512 (CTA = level-8 subtree). The 23 input rows
//          (9 upper + 2 l9 + 4 l10 + 8 l11) are split over 4 row-groups of
//          128 threads as INDEPENDENT LDG.128s (<=6/thread, no level chain),
//          staged in SMEM, combined once -> 8 level-11 cum rows to g_cum.
//          sq levels 0..11 folded at load (owner-CTA gating) -> g_sqE[256].
//  stream: 2048 CTAs x 256 (tile = level-11 subtree, 8 leaves), 30KB smem:
//          mb0(TMA): cum row + lvl12 pair + lvl13 quad (14KB)
//          mb1(TMA): 8 leaf delta rows (16KB);  x via 4 indep LDG.128 at dot.
//          sq levels 12..14 fused -> g_part[2048]; fence+counter last-CTA
//          reduces g_sqE+g_part in fixed order. Deterministic (no data atomics).

#define DIM 512
#define N_LEAVES 16384
#define NTILES 2048

__device__ __align__(128) float g_cum[NTILES * DIM];  // level-11 cums (4MB)
__device__ float g_sqE[256];
__device__ float g_part[NTILES];
__device__ unsigned int g_count = 0;

__device__ __forceinline__ float warp_sum(float v) {
#pragma unroll
    for (int o = 16; o > 0; o >>= 1) v += __shfl_down_sync(0xffffffffu, v, o);
    return v;
}
__device__ __forceinline__ float inv_branch(const float* __restrict__ h, int n) {
    return 1.0f / fmaxf(h[n] - h[(n - 1) >> 1], 1e-7f);
}
__device__ __forceinline__ float sq4(float4 v) {
    return fmaf(v.x, v.x, fmaf(v.y, v.y, fmaf(v.z, v.z, v.w * v.w)));
}
__device__ __forceinline__ float4 add4(float4 a, float4 b) {
    return make_float4(a.x + b.x, a.y + b.y, a.z + b.z, a.w + b.w);
}
__device__ __forceinline__ void bulk_cp(unsigned dst, const float* src, unsigned bytes, unsigned mb) {
    asm volatile("cp.async.bulk.shared::cta.global.mbarrier::complete_tx::bytes [%0], [%1], %2, [%3];"
                 :: "r"(dst), "l"(src), "r"(bytes), "r"(mb) : "memory");
}
__device__ __forceinline__ void mb_wait(unsigned mb) {
    asm volatile(
        "{\n\t.reg .pred p;\n\t"
        "W_%=:\n\t"
        "mbarrier.try_wait.parity.acquire.cta.shared::cta.b64 p, [%0], 0;\n\t"
        "@!p bra W_%=;\n\t}" :: "r"(mb) : "memory");
}

// ---------------- fused expand: levels 0..11, chainless ---------------------
// smem float4 rows: UP 3 @0, L9 2 @384, L10 4 @640, L11 8 @1152  (34KB)
__global__ __launch_bounds__(512) void expand_kernel(const float* __restrict__ deltas,
                                                     const float* __restrict__ heights) {
    __shared__ float4 sm[2176];
    __shared__ float red[16];

    const int r    = blockIdx.x;          // level-8 subtree 0..255
    const int tid  = threadIdx.x;
    const int q    = tid >> 7;            // row-group 0..3
    const int col  = tid & 127;           // float4 column
    const int w    = tid >> 5;
    const int lane = tid & 31;

    int anc[9];
    anc[8] = 255 + r;
#pragma unroll
    for (int l = 8; l > 0; --l) anc[l - 1] = (anc[l] - 1) >> 1;

    const int n9b  = 511 + 2 * r;
    const int n10b = 1023 + 4 * r;
    const int n11b = 2047 + 8 * r;

    float sqacc = 0.f;

    // ---- group loads: all independent --------------------------------------
    if (q < 3) {
        // 3 upper rows + 1 mid row + 2 l11 rows
        float4 u0 = ((const float4*)(deltas + (size_t)anc[3 * q + 0] * DIM))[col];
        float4 u1 = ((const float4*)(deltas + (size_t)anc[3 * q + 1] * DIM))[col];
        float4 u2 = ((const float4*)(deltas + (size_t)anc[3 * q + 2] * DIM))[col];
        int nm;                                   // mid row node
        if (q == 0) nm = n9b;                     // l9_0
        else if (q == 1) nm = n9b + 1;            // l9_1
        else nm = n10b;                           // l10_0
        float4 vm = ((const float4*)(deltas + (size_t)nm * DIM))[col];
        float4 va = ((const float4*)(deltas + (size_t)(n11b + 2 * q) * DIM))[col];
        float4 vb = ((const float4*)(deltas + (size_t)(n11b + 2 * q + 1) * DIM))[col];

        // sq folding (owner-CTA gating for shared upper rows)
#pragma unroll
        for (int k = 0; k < 3; ++k) {
            const int l = 3 * q + k;
            float4 u = (k == 0) ? u0 : (k == 1) ? u1 : u2;
            if ((r & ((1 << (8 - l)) - 1)) == 0) {
                float inv = (l == 0) ? 1.0f : inv_branch(heights, anc[l]);
                sqacc = fmaf(sq4(u), inv, sqacc);
            }
        }
        sqacc = fmaf(sq4(vm), inv_branch(heights, nm), sqacc);
        sqacc = fmaf(sq4(va), inv_branch(heights, n11b + 2 * q), sqacc);
        sqacc = fmaf(sq4(vb), inv_branch(heights, n11b + 2 * q + 1), sqacc);

        sm[q * 128 + col] = add4(add4(u0, u1), u2);          // UP partial
        if (q == 0)      sm[384 + col] = vm;                 // L9_0
        else if (q == 1) sm[384 + 128 + col] = vm;           // L9_1
        else             sm[640 + col] = vm;                 // L10_0
        sm[1152 + (2 * q) * 128 + col]     = va;             // L11
        sm[1152 + (2 * q + 1) * 128 + col] = vb;
    } else {
        // 3 l10 rows + 2 l11 rows
        float4 m1 = ((const float4*)(deltas + (size_t)(n10b + 1) * DIM))[col];
        float4 m2 = ((const float4*)(deltas + (size_t)(n10b + 2) * DIM))[col];
        float4 m3 = ((const float4*)(deltas + (size_t)(n10b + 3) * DIM))[col];
        float4 va = ((const float4*)(deltas + (size_t)(n11b + 6) * DIM))[col];
        float4 vb = ((const float4*)(deltas + (size_t)(n11b + 7) * DIM))[col];

        sqacc = fmaf(sq4(m1), inv_branch(heights, n10b + 1), sqacc);
        sqacc = fmaf(sq4(m2), inv_branch(heights, n10b + 2), sqacc);
        sqacc = fmaf(sq4(m3), inv_branch(heights, n10b + 3), sqacc);
        sqacc = fmaf(sq4(va), inv_branch(heights, n11b + 6), sqacc);
        sqacc = fmaf(sq4(vb), inv_branch(heights, n11b + 7), sqacc);

        sm[640 + 128 + col] = m1;
        sm[640 + 256 + col] = m2;
        sm[640 + 384 + col] = m3;
        sm[1152 + 6 * 128 + col] = va;
        sm[1152 + 7 * 128 + col] = vb;
    }
    __syncthreads();

    // ---- combine: group q emits rows j = 2q, 2q+1 ---------------------------
    float4 up = add4(add4(sm[col], sm[128 + col]), sm[256 + col]);
#pragma unroll
    for (int k = 0; k < 2; ++k) {
        const int j = 2 * q + k;
        float4 v = add4(up, sm[384 + (j >> 2) * 128 + col]);
        v = add4(v, sm[640 + (j >> 1) * 128 + col]);
        v = add4(v, sm[1152 + j * 128 + col]);
        ((float4*)(g_cum + (size_t)(8 * r + j) * DIM))[col] = v;
    }

    sqacc = warp_sum(sqacc);
    if (lane == 0) red[w] = sqacc;
    __syncthreads();
    if (tid == 0) {
        float t = 0.f;
#pragma unroll
        for (int j = 0; j < 16; ++j) t += red[j];
        g_sqE[r] = t;
    }
}

// ---------------- stream: leaves + dots + final reduce ----------------------
// smem float4 offsets: CUM 0 (1 row), D12 128 (2), D13 384 (4), DL 896 (8)
__global__ __launch_bounds__(256) void stream_kernel(const float* __restrict__ x,
                                                     const float* __restrict__ deltas,
                                                     const float* __restrict__ heights,
                                                     float* __restrict__ out) {
    __shared__ float4 sm[1920];       // 30 KB
    __shared__ float  redL[32];
    __shared__ float  redS[8];
    __shared__ int    is_last;
    __shared__ __align__(8) unsigned long long mbar[2];

    const int b    = blockIdx.x;      // tile = level-11 subtree
    const int tid  = threadIdx.x;
    const int col  = tid & 127;
    const int g    = tid >> 7;        // slice 0/1
    const int w    = tid >> 5;
    const int ws   = w & 3;
    const int lane = tid & 31;

    const unsigned mb0 = (unsigned)__cvta_generic_to_shared(&mbar[0]);
    const unsigned mb1 = (unsigned)__cvta_generic_to_shared(&mbar[1]);
    const unsigned smb = (unsigned)__cvta_generic_to_shared(sm);

    if (tid == 0) {
        asm volatile("mbarrier.init.shared.b64 [%0], %1;" :: "r"(mb0), "r"(1));
        asm volatile("mbarrier.init.shared.b64 [%0], %1;" :: "r"(mb1), "r"(1));
        asm volatile("fence.proxy.async.shared::cta;" ::: "memory");
        asm volatile("mbarrier.arrive.expect_tx.shared.b64 _, [%0], %1;" :: "r"(mb0), "r"(14336u));
        asm volatile("mbarrier.arrive.expect_tx.shared.b64 _, [%0], %1;" :: "r"(mb1), "r"(16384u));
        bulk_cp(smb + 0   * 16, g_cum + (size_t)b * DIM,                    2048u,  mb0);
        bulk_cp(smb + 128 * 16, deltas + (size_t)(4095 + 2 * b) * DIM,      4096u,  mb0);
        bulk_cp(smb + 384 * 16, deltas + (size_t)(8191 + 4 * b) * DIM,      8192u,  mb0);
        bulk_cp(smb + 896 * 16, deltas + (size_t)(N_LEAVES - 1 + 8 * b) * DIM, 16384u, mb1);
    }
    __syncthreads();

    // scalar inv factors (broadcast loads; overlap with TMA flight)
    const float inv12 = inv_branch(heights, 4095 + 2 * b + g);
    float inv13[2], inv14[4];
#pragma unroll
    for (int j = 0; j < 2; ++j) inv13[j] = inv_branch(heights, 8191 + 4 * b + 2 * g + j);
#pragma unroll
    for (int j = 0; j < 4; ++j) inv14[j] = inv_branch(heights, N_LEAVES - 1 + 8 * b + 4 * g + j);

    float sqacc = 0.f;

    // ---- weight path (mb0) --------------------------------------------------
    mb_wait(mb0);
    float4 c12;
    {
        float4 v = sm[128 + g * 128 + col];
        sqacc = fmaf(sq4(v), inv12, sqacc);
        c12 = add4(sm[col], v);
    }
    float4 c13[2];
#pragma unroll
    for (int j = 0; j < 2; ++j) {
        float4 v = sm[384 + (2 * g + j) * 128 + col];
        sqacc = fmaf(sq4(v), inv13[j], sqacc);
        c13[j] = add4(c12, v);
    }

    // ---- leaves (mb1) + x via independent LDG.128 ---------------------------
    mb_wait(mb1);
    float4 xv[4];
#pragma unroll
    for (int j = 0; j < 4; ++j)       // 4 independent global loads, issued first
        xv[j] = ((const float4*)(x + (size_t)(8 * b + 4 * g + j) * DIM))[col];

    float acc[4];
#pragma unroll
    for (int j = 0; j < 4; ++j) {
        const int li = 4 * g + j;
        float4 dv = sm[896 + li * 128 + col];
        sqacc = fmaf(sq4(dv), inv14[j], sqacc);
        float4 wv = add4(c13[j >> 1], dv);
        float t;
        t = xv[j].x * wv.x;
        t = fmaf(xv[j].y, wv.y, t);
        t = fmaf(xv[j].z, wv.z, t);
        t = fmaf(xv[j].w, wv.w, t);
        acc[j] = warp_sum(t);
    }
    if (lane == 0) {
#pragma unroll
        for (int j = 0; j < 4; ++j) redL[(g * 4 + j) * 4 + ws] = acc[j];
    }

    sqacc = warp_sum(sqacc);
    if (lane == 0) redS[w] = sqacc;
    __syncthreads();

    if (tid < 8) {
        float r = redL[tid * 4] + redL[tid * 4 + 1] + redL[tid * 4 + 2] + redL[tid * 4 + 3];
        out[8 * b + tid] = r;
    }
    if (tid == 0) {
        float t = 0.f;
#pragma unroll
        for (int j = 0; j < 8; ++j) t += redS[j];
        g_part[b] = t;
        __threadfence();
        unsigned prev = atomicAdd(&g_count, 1u);
        is_last = (prev == NTILES - 1) ? 1 : 0;
    }
    __syncthreads();

    // ---- last CTA: deterministic final reduce (fixed order) -----------------
    if (is_last) {
        const volatile float* gE = g_sqE;
        const volatile float* gp = g_part;
        float s = (tid < 256) ? gE[tid] : 0.f;
#pragma unroll
        for (int r = 0; r < 8; ++r) s += gp[tid + 256 * r];
        s = warp_sum(s);
        if (lane == 0) redS[w] = s;
        __syncthreads();
        if (tid == 0) {
            float t = 0.f;
#pragma unroll
            for (int j = 0; j < 8; ++j) t += redS[j];
            out[N_LEAVES] = t;
            g_count = 0;              // reset for next graph replay
        }
    }
}

extern "C" void kernel_launch(void* const* d_in, const int* in_sizes, int n_in,
                              void* d_out, int out_size) {
    const float* x       = (const float*)d_in[0];
    const float* deltas  = (const float*)d_in[1];
    const float* heights = (const float*)d_in[2];
    float* out = (float*)d_out;

    expand_kernel<<<256, 512>>>(deltas, heights);
    stream_kernel<<<NTILES, 256>>>(x, deltas, heights, out);
}